// round 8
// baseline (speedup 1.0000x reference)
#include <cuda_runtime.h>
#include <cstdint>
#include <math.h>

// Level 0: [4, 64, 4096], level 1: [4, 128, 1024]; 64x64 upper-tri tiles.
#define NTILE0 64
#define NTILE1 16
#define NBLK0 (NTILE0 * (NTILE0 + 1) / 2)   // 2080
#define NBLK1 (NTILE1 * (NTILE1 + 1) / 2)   // 136
#define NBLK  (NBLK0 + NBLK1)

#define KC 16                           // k-rows per chunk
#define PADS 72                         // 64 + 8 pad: frag banks (8*lr+lq) all distinct
#define SIDE_STRIDE (KC * PADS)         // 1152 floats per combo per side
#define BUF_FLOATS (16 * SIDE_STRIDE)   // A(8) + B(8) combos = 18432 floats
#define BUF_BYTES (BUF_FLOATS * 4)      // 73728 B
#define NSTAGE 3
#define SMEM_BYTES (NSTAGE * BUF_BYTES) // 221184 B (ring; reused by epilogue)
#define EX_STRIDE 68                    // [c][i][j] row stride

#define NTHR 1024

__device__ double g_sum = 0.0;
__device__ unsigned g_cnt = 0u;

__device__ __forceinline__ uint32_t smem_u32(const void* p) {
    return (uint32_t)__cvta_generic_to_shared(p);
}
__device__ __forceinline__ void cp16(uint32_t dst, const void* src) {
    asm volatile("cp.async.ca.shared.global [%0], [%1], 16;" :: "r"(dst), "l"(src));
}
#define CP_COMMIT() asm volatile("cp.async.commit_group;" ::: "memory")
#define CP_WAIT(n)  asm volatile("cp.async.wait_group %0;" :: "n"(n) : "memory")

__device__ __forceinline__ void mma_tf32(float* d, const uint32_t* a, const uint32_t* b) {
    asm volatile(
        "mma.sync.aligned.m16n8k8.row.col.f32.tf32.tf32.f32 "
        "{%0,%1,%2,%3}, {%4,%5,%6,%7}, {%8,%9}, {%0,%1,%2,%3};"
        : "+f"(d[0]), "+f"(d[1]), "+f"(d[2]), "+f"(d[3])
        : "r"(a[0]), "r"(a[1]), "r"(a[2]), "r"(a[3]), "r"(b[0]), "r"(b[1]));
}

// Stage one chunk (16 k-rows x 64 cols x 8 combos, both sides), 1024 threads.
template<int C, int HW>
__device__ __forceinline__ void stage_chunk(const float* __restrict__ f1,
                                            const float* __restrict__ f2,
                                            int k0, int I0, int J0,
                                            uint32_t buf_u, int tid)
{
    const uint32_t bufB_u = buf_u + 8 * SIDE_STRIDE * 4;
    #pragma unroll
    for (int it = 0; it < 2; it++) {
        int l = it * NTHR + tid;
        int i4 = l & 15, kk = (l >> 4) & 15, combo = l >> 8;
        const float* src = (combo < 4) ? f1 : f2;
        const float* p = src + ((size_t)(combo & 3) * C + k0 + kk) * HW + I0 + i4 * 4;
        cp16(buf_u + (combo * SIDE_STRIDE + kk * PADS + i4 * 4) * 4, p);
    }
    #pragma unroll
    for (int it = 0; it < 2; it++) {
        int l = it * NTHR + tid;
        int j4 = l & 15, kk = (l >> 4) & 15, combo = l >> 8;
        const float* src = (combo < 4) ? f1 : f2;
        const float* p = src + ((size_t)(combo & 3) * C + k0 + kk) * HW + J0 + j4 * 4;
        cp16(bufB_u + (combo * SIDE_STRIDE + kk * PADS + j4 * 4) * 4, p);
    }
}

// One 64x64 (i,j) upper-tri tile. 32 warps = 2 features x 4 batches x 4
// m-quarters; each warp computes one combo's 16x64 gram patch (32 acc regs).
// Epilogue: 8 gram planes exchanged via smem, per-element batch-softmax +
// |A1-A2| over 1024 threads.
template<int C, int HW, int NT>
__device__ __forceinline__ void gram_tile(const float* __restrict__ f1,
                                          const float* __restrict__ f2,
                                          int blk, uint32_t* smem,
                                          double lvl_w, float* out)
{
    constexpr int CH = C / KC;
    const int tid  = threadIdx.x;
    const int wid  = tid >> 5;
    const int lane = tid & 31;
    const int cb   = wid & 3;         // batch
    const int pq   = (wid >> 2) & 3;  // m-quarter (16 rows)
    const int g    = wid >> 4;        // 0: feature1, 1: feature2
    const int combo = g * 4 + cb;

    int rem = blk, ti = 0;
    while (rem >= NT - ti) { rem -= NT - ti; ti++; }
    const int tj = ti + rem;
    const int I0 = ti * 64;
    const int J0 = tj * 64;

    const uint32_t smem_base = smem_u32(smem);
    const int lq = lane >> 2;
    const int lr = lane & 3;

    float acc[8][4];   // [nt][e]
    #pragma unroll
    for (int nt = 0; nt < 8; nt++)
        #pragma unroll
        for (int e = 0; e < 4; e++) acc[nt][e] = 0.f;

    // Prologue: stage chunks 0 and 1.
    stage_chunk<C, HW>(f1, f2, 0, I0, J0, smem_base, tid);
    CP_COMMIT();
    stage_chunk<C, HW>(f1, f2, KC, I0, J0, smem_base + BUF_BYTES, tid);
    CP_COMMIT();

    int buf_idx = 0;
    for (int ch = 0; ch < CH; ch++) {
        if (ch + 1 < CH) { CP_WAIT(1); } else { CP_WAIT(0); }
        __syncthreads();   // chunk ch ready; everyone done with chunk ch-1's buffer

        if (ch + 2 < CH) {
            int nb = buf_idx + 2; if (nb >= NSTAGE) nb -= NSTAGE;
            stage_chunk<C, HW>(f1, f2, (ch + 2) * KC, I0, J0,
                               smem_base + nb * BUF_BYTES, tid);
            CP_COMMIT();
        }

        const uint32_t* cA = smem + buf_idx * BUF_FLOATS + combo * SIDE_STRIDE;
        const uint32_t* cB = smem + buf_idx * BUF_FLOATS + (8 + combo) * SIDE_STRIDE;

        #pragma unroll
        for (int s = 0; s < 2; s++) {
            uint32_t afr[4];
            #pragma unroll
            for (int e = 0; e < 4; e++) {
                int kk = s * 8 + lr + 4 * (e >> 1);
                int i  = pq * 16 + lq + 8 * (e & 1);
                afr[e] = cA[kk * PADS + i];
            }
            #pragma unroll
            for (int nt = 0; nt < 8; nt++) {
                uint32_t bfr[2];
                int j = nt * 8 + lq;
                bfr[0] = cB[(s * 8 + lr) * PADS + j];
                bfr[1] = cB[(s * 8 + lr + 4) * PADS + j];
                mma_tf32(acc[nt], afr, bfr);
            }
        }

        buf_idx++; if (buf_idx >= NSTAGE) buf_idx = 0;
    }
    __syncthreads();   // all compute done before reusing smem for exchange

    // ---- epilogue: write the 8 gram planes [c][64][EX_STRIDE] ----
    float* ex = (float*)smem;
    #pragma unroll
    for (int nt = 0; nt < 8; nt++)
        #pragma unroll
        for (int h = 0; h < 2; h++) {
            int i = pq * 16 + 8 * h + lq;
            int j = nt * 8 + 2 * lr;
            *(float2*)&ex[(combo * 64 + i) * EX_STRIDE + j] =
                make_float2(acc[nt][2 * h], acc[nt][2 * h + 1]);
        }
    __syncthreads();

    // ---- per-element softmax over batch + |diff|: 4 elements per thread ----
    const int ie = tid >> 4;          // 0..63
    const int jb = (tid & 15) * 4;    // 0..60
    const int gi = I0 + ie;
    float v[8][4];
    #pragma unroll
    for (int c = 0; c < 8; c++)
        *(float4*)v[c] = *(const float4*)&ex[(c * 64 + ie) * EX_STRIDE + jb];
    float lsum = 0.f;
    #pragma unroll
    for (int e = 0; e < 4; e++) {
        const int gj = J0 + jb + e;
        float w = (gi < gj) ? 2.f : ((gi == gj) ? 1.f : 0.f);
        float x0 = v[0][e], x1 = v[1][e], x2 = v[2][e], x3 = v[3][e];
        float y0 = v[4][e], y1 = v[5][e], y2 = v[6][e], y3 = v[7][e];
        float m1 = fmaxf(fmaxf(x0, x1), fmaxf(x2, x3));
        float m2 = fmaxf(fmaxf(y0, y1), fmaxf(y2, y3));
        float e0 = __expf(x0 - m1), e1 = __expf(x1 - m1);
        float e2 = __expf(x2 - m1), e3 = __expf(x3 - m1);
        float h0 = __expf(y0 - m2), h1 = __expf(y1 - m2);
        float h2 = __expf(y2 - m2), h3 = __expf(y3 - m2);
        float s1 = 1.0f / (e0 + e1 + e2 + e3);
        float s2 = 1.0f / (h0 + h1 + h2 + h3);
        lsum += w * (fabsf(e0 * s1 - h0 * s2) + fabsf(e1 * s1 - h1 * s2)
                   + fabsf(e2 * s1 - h2 * s2) + fabsf(e3 * s1 - h3 * s2));
    }

    #pragma unroll
    for (int o = 16; o > 0; o >>= 1) lsum += __shfl_xor_sync(0xffffffffu, lsum, o);
    __shared__ float red[32];
    if (lane == 0) red[wid] = lsum;
    __syncthreads();
    if (tid == 0) {
        float bs = 0.f;
        #pragma unroll
        for (int r = 0; r < 32; r++) bs += red[r];
        atomicAdd(&g_sum, (double)bs * lvl_w);
        __threadfence();
        unsigned t = atomicAdd(&g_cnt, 1u);
        if (t == (unsigned)(NBLK - 1)) {
            out[0] = (float)g_sum;     // all partials visible (counter + fence)
            g_sum = 0.0;               // reset for next graph replay
            g_cnt = 0u;
        }
    }
}

// Level-1 CTAs (8 chunks, long) scheduled first to avoid a long tail wave.
__global__ __launch_bounds__(NTHR, 1)
void fused_gram_loss_kernel(const float* __restrict__ f1_0, const float* __restrict__ f2_0,
                            const float* __restrict__ f1_1, const float* __restrict__ f2_1,
                            float* __restrict__ out)
{
    extern __shared__ uint32_t smem[];
    const double w0 = 0.5 / (4.0 * 4096.0 * 4096.0);
    const double w1 = 0.5 / (4.0 * 1024.0 * 1024.0);
    if (blockIdx.x < NBLK1)
        gram_tile<128, 1024, NTILE1>(f1_1, f2_1, blockIdx.x, smem, w1, out);
    else
        gram_tile<64, 4096, NTILE0>(f1_0, f2_0, blockIdx.x - NBLK1, smem, w0, out);
}

extern "C" void kernel_launch(void* const* d_in, const int* in_sizes, int n_in,
                              void* d_out, int out_size)
{
    const float* fea1_0 = (const float*)d_in[0];  // [4, 64, 64, 64]
    const float* fea1_1 = (const float*)d_in[1];  // [4, 128, 32, 32]
    const float* fea2_0 = (const float*)d_in[2];
    const float* fea2_1 = (const float*)d_in[3];
    float* out = (float*)d_out;

    cudaFuncSetAttribute(fused_gram_loss_kernel,
                         cudaFuncAttributeMaxDynamicSharedMemorySize, SMEM_BYTES);
    fused_gram_loss_kernel<<<NBLK, NTHR, SMEM_BYTES>>>(fea1_0, fea2_0, fea1_1, fea2_1, out);
}

// round 9
// speedup vs baseline: 1.2227x; 1.2227x over previous
#include <cuda_runtime.h>
#include <cstdint>
#include <math.h>

// Level 0: [4, 64, 4096], level 1: [4, 128, 1024]; 64x32 upper-tri tiles.
// Tiles kept when tj >= 2*ti (tile touches upper triangle).
#define NTJ0 128
#define NTJ1 32
#define NBLK0 4160   // sum_{ti=0..63} (128 - 2*ti)
#define NBLK1 272    // sum_{ti=0..15} (32 - 2*ti)
#define NBLK  (NBLK0 + NBLK1)

#define KC 8                            // k-rows per chunk
#define PADS_A 72                       // 64+8: frag bank = 8*lr+lq, all distinct
#define PADS_B 40                       // 32+8: 40 mod 32 = 8 -> same pattern
#define A_STRIDE (KC * PADS_A)          // 576 floats per combo
#define B_STRIDE (KC * PADS_B)          // 320 floats per combo
#define BUF_FLOATS (8 * (A_STRIDE + B_STRIDE))   // 7168
#define BUF_BYTES (BUF_FLOATS * 4)      // 28672
#define NSTAGE 3
#define SMEM_BYTES (NSTAGE * BUF_BYTES) // 86016 (ring; reused by epilogue)
#define EX_STRIDE 36                    // [c][i][j] row stride (144B, 16B-aligned)

#define NTHR 512

__device__ double g_sum = 0.0;
__device__ unsigned g_cnt = 0u;

__device__ __forceinline__ uint32_t smem_u32(const void* p) {
    return (uint32_t)__cvta_generic_to_shared(p);
}
__device__ __forceinline__ void cp16(uint32_t dst, const void* src) {
    asm volatile("cp.async.ca.shared.global [%0], [%1], 16;" :: "r"(dst), "l"(src));
}
#define CP_COMMIT() asm volatile("cp.async.commit_group;" ::: "memory")
#define CP_WAIT(n)  asm volatile("cp.async.wait_group %0;" :: "n"(n) : "memory")

__device__ __forceinline__ void mma_tf32(float* d, const uint32_t* a, const uint32_t* b) {
    asm volatile(
        "mma.sync.aligned.m16n8k8.row.col.f32.tf32.tf32.f32 "
        "{%0,%1,%2,%3}, {%4,%5,%6,%7}, {%8,%9}, {%0,%1,%2,%3};"
        : "+f"(d[0]), "+f"(d[1]), "+f"(d[2]), "+f"(d[3])
        : "r"(a[0]), "r"(a[1]), "r"(a[2]), "r"(a[3]), "r"(b[0]), "r"(b[1]));
}

// Stage one chunk (8 k-rows; A: 64 i-cols, B: 32 j-cols; 8 combos), 512 threads.
template<int C, int HW>
__device__ __forceinline__ void stage_chunk(const float* __restrict__ f1,
                                            const float* __restrict__ f2,
                                            int k0, int I0, int J0,
                                            uint32_t buf_u, int tid)
{
    const uint32_t bufB_u = buf_u + 8 * A_STRIDE * 4;
    #pragma unroll
    for (int it = 0; it < 2; it++) {            // A: 1024 float4
        int l = it * NTHR + tid;
        int i4 = l & 15, kk = (l >> 4) & 7, combo = l >> 7;
        const float* src = (combo < 4) ? f1 : f2;
        const float* p = src + ((size_t)(combo & 3) * C + k0 + kk) * HW + I0 + i4 * 4;
        cp16(buf_u + (combo * A_STRIDE + kk * PADS_A + i4 * 4) * 4, p);
    }
    {                                            // B: 512 float4
        int j4 = tid & 7, kk = (tid >> 3) & 7, combo = tid >> 6;
        const float* src = (combo < 4) ? f1 : f2;
        const float* p = src + ((size_t)(combo & 3) * C + k0 + kk) * HW + J0 + j4 * 4;
        cp16(bufB_u + (combo * B_STRIDE + kk * PADS_B + j4 * 4) * 4, p);
    }
}

// One 64x32 (i,j) tile. 16 warps = 2 features x 4 batches x 2 m-halves; each
// warp computes one combo's 32x32 gram patch (32 acc regs). Epilogue: 8 gram
// planes exchanged via smem, per-element batch-softmax + |A1-A2|.
template<int C, int HW, int NTJ>
__device__ __forceinline__ void gram_tile(const float* __restrict__ f1,
                                          const float* __restrict__ f2,
                                          int blk, uint32_t* smem,
                                          double lvl_w, float* out)
{
    constexpr int CH = C / KC;
    const int tid  = threadIdx.x;
    const int wid  = tid >> 5;
    const int lane = tid & 31;
    const int cb   = wid & 3;         // batch
    const int pm   = (wid >> 2) & 1;  // m-half (32 rows)
    const int g    = wid >> 3;        // 0: feature1, 1: feature2
    const int combo = g * 4 + cb;

    int rem = blk, ti = 0;
    while (rem >= NTJ - 2 * ti) { rem -= NTJ - 2 * ti; ti++; }
    const int tj = 2 * ti + rem;
    const int I0 = ti * 64;
    const int J0 = tj * 32;

    const uint32_t smem_base = smem_u32(smem);
    const int lq = lane >> 2;
    const int lr = lane & 3;

    float acc[2][4][4];   // [mt][nt][e]
    #pragma unroll
    for (int mt = 0; mt < 2; mt++)
        #pragma unroll
        for (int nt = 0; nt < 4; nt++)
            #pragma unroll
            for (int e = 0; e < 4; e++) acc[mt][nt][e] = 0.f;

    stage_chunk<C, HW>(f1, f2, 0, I0, J0, smem_base, tid);
    CP_COMMIT();
    stage_chunk<C, HW>(f1, f2, KC, I0, J0, smem_base + BUF_BYTES, tid);
    CP_COMMIT();

    int buf_idx = 0;
    for (int ch = 0; ch < CH; ch++) {
        if (ch + 1 < CH) { CP_WAIT(1); } else { CP_WAIT(0); }
        __syncthreads();   // chunk ch ready; everyone done with chunk ch-1's buffer

        if (ch + 2 < CH) {
            int nb = buf_idx + 2; if (nb >= NSTAGE) nb -= NSTAGE;
            stage_chunk<C, HW>(f1, f2, (ch + 2) * KC, I0, J0,
                               smem_base + nb * BUF_BYTES, tid);
            CP_COMMIT();
        }

        const uint32_t* cA = smem + buf_idx * BUF_FLOATS + combo * A_STRIDE;
        const uint32_t* cB = smem + buf_idx * BUF_FLOATS + 8 * A_STRIDE + combo * B_STRIDE;

        uint32_t afr[2][4];
        #pragma unroll
        for (int mt = 0; mt < 2; mt++)
            #pragma unroll
            for (int e = 0; e < 4; e++) {
                int kk = lr + 4 * (e >> 1);
                int i  = pm * 32 + mt * 16 + lq + 8 * (e & 1);
                afr[mt][e] = cA[kk * PADS_A + i];
            }
        #pragma unroll
        for (int nt = 0; nt < 4; nt++) {
            uint32_t bfr[2];
            int j = nt * 8 + lq;
            bfr[0] = cB[lr * PADS_B + j];
            bfr[1] = cB[(lr + 4) * PADS_B + j];
            mma_tf32(acc[0][nt], afr[0], bfr);
            mma_tf32(acc[1][nt], afr[1], bfr);
        }

        buf_idx++; if (buf_idx >= NSTAGE) buf_idx = 0;
    }
    __syncthreads();   // all compute done before reusing smem for exchange

    // ---- epilogue: write the 8 gram planes [c][64][EX_STRIDE] ----
    float* ex = (float*)smem;
    #pragma unroll
    for (int mt = 0; mt < 2; mt++)
        #pragma unroll
        for (int nt = 0; nt < 4; nt++)
            #pragma unroll
            for (int h = 0; h < 2; h++) {
                int i = pm * 32 + mt * 16 + 8 * h + lq;
                int j = nt * 8 + 2 * lr;
                *(float2*)&ex[(combo * 64 + i) * EX_STRIDE + j] =
                    make_float2(acc[mt][nt][2 * h], acc[mt][nt][2 * h + 1]);
            }
    __syncthreads();

    // ---- per-element softmax over batch + |diff|: 4 elements per thread ----
    const int ie = tid >> 3;          // 0..63
    const int jb = (tid & 7) * 4;     // 0..28
    const int gi = I0 + ie;
    float v[8][4];
    #pragma unroll
    for (int c = 0; c < 8; c++)
        *(float4*)v[c] = *(const float4*)&ex[(c * 64 + ie) * EX_STRIDE + jb];
    float lsum = 0.f;
    #pragma unroll
    for (int e = 0; e < 4; e++) {
        const int gj = J0 + jb + e;
        float w = (gi < gj) ? 2.f : ((gi == gj) ? 1.f : 0.f);
        float x0 = v[0][e], x1 = v[1][e], x2 = v[2][e], x3 = v[3][e];
        float y0 = v[4][e], y1 = v[5][e], y2 = v[6][e], y3 = v[7][e];
        float m1 = fmaxf(fmaxf(x0, x1), fmaxf(x2, x3));
        float m2 = fmaxf(fmaxf(y0, y1), fmaxf(y2, y3));
        float e0 = __expf(x0 - m1), e1 = __expf(x1 - m1);
        float e2 = __expf(x2 - m1), e3 = __expf(x3 - m1);
        float h0 = __expf(y0 - m2), h1 = __expf(y1 - m2);
        float h2 = __expf(y2 - m2), h3 = __expf(y3 - m2);
        float s1 = 1.0f / (e0 + e1 + e2 + e3);
        float s2 = 1.0f / (h0 + h1 + h2 + h3);
        lsum += w * (fabsf(e0 * s1 - h0 * s2) + fabsf(e1 * s1 - h1 * s2)
                   + fabsf(e2 * s1 - h2 * s2) + fabsf(e3 * s1 - h3 * s2));
    }

    #pragma unroll
    for (int o = 16; o > 0; o >>= 1) lsum += __shfl_xor_sync(0xffffffffu, lsum, o);
    __shared__ float red[16];
    if (lane == 0) red[wid] = lsum;
    __syncthreads();
    if (tid == 0) {
        float bs = 0.f;
        #pragma unroll
        for (int r = 0; r < 16; r++) bs += red[r];
        atomicAdd(&g_sum, (double)bs * lvl_w);
        __threadfence();
        unsigned t = atomicAdd(&g_cnt, 1u);
        if (t == (unsigned)(NBLK - 1)) {
            out[0] = (float)g_sum;     // all partials visible (counter + fence)
            g_sum = 0.0;               // reset for next graph replay
            g_cnt = 0u;
        }
    }
}

// Level-1 CTAs (16 chunks, long) scheduled first to avoid a long tail wave.
__global__ __launch_bounds__(NTHR, 2)
void fused_gram_loss_kernel(const float* __restrict__ f1_0, const float* __restrict__ f2_0,
                            const float* __restrict__ f1_1, const float* __restrict__ f2_1,
                            float* __restrict__ out)
{
    extern __shared__ uint32_t smem[];
    const double w0 = 0.5 / (4.0 * 4096.0 * 4096.0);
    const double w1 = 0.5 / (4.0 * 1024.0 * 1024.0);
    if (blockIdx.x < NBLK1)
        gram_tile<128, 1024, NTJ1>(f1_1, f2_1, blockIdx.x, smem, w1, out);
    else
        gram_tile<64, 4096, NTJ0>(f1_0, f2_0, blockIdx.x - NBLK1, smem, w0, out);
}

extern "C" void kernel_launch(void* const* d_in, const int* in_sizes, int n_in,
                              void* d_out, int out_size)
{
    const float* fea1_0 = (const float*)d_in[0];  // [4, 64, 64, 64]
    const float* fea1_1 = (const float*)d_in[1];  // [4, 128, 32, 32]
    const float* fea2_0 = (const float*)d_in[2];
    const float* fea2_1 = (const float*)d_in[3];
    float* out = (float*)d_out;

    cudaFuncSetAttribute(fused_gram_loss_kernel,
                         cudaFuncAttributeMaxDynamicSharedMemorySize, SMEM_BYTES);
    fused_gram_loss_kernel<<<NBLK, NTHR, SMEM_BYTES>>>(fea1_0, fea2_0, fea1_1, fea2_1, out);
}